// round 3
// baseline (speedup 1.0000x reference)
#include <cuda_runtime.h>
#include <cuda_bf16.h>
#include <math.h>

// Problem constants
#define NN 8192
#define KK 64
#define NB 1024                 // buckets
#define XLO (-6.0f)
#define BW_INV (1024.0f / 12.0f)   // 1/bucket_width = 85.3333
#define RWIN 10                 // +/- bucket window: 10*0.01172 > 0.1034 support radius

// exp(-8192*d^2) == 0.0f (fp32) for |d| > 0.10335; window excludes only those.
#define NEG_HALF_INV_BW2 (-8192.0f)

// Scratch (__device__ globals; no allocations allowed)
__device__ int   g_hist[NB];      // zero-init by runtime; re-zeroed each call in scan kernel
__device__ int   g_cursor[NB];
__device__ int   g_off[NB + 1];
__device__ float g_sv[NN];        // bucket-grouped, intra-bucket value-sorted x
__device__ float g_diff[NN];      // (mix - data_pdf)^2 per sorted element
__device__ float g_a[KK], g_c[KK], g_mu[KK];

__device__ __forceinline__ int bucket_of(float v) {
    int b = (int)floorf((v - XLO) * BW_INV);
    return min(max(b, 0), NB - 1);
}

// ---------------------------------------------------------------------------
// K1: histogram of bucket counts. 8 blocks x 1024 threads.
// ---------------------------------------------------------------------------
__global__ void __launch_bounds__(1024)
k_hist(const float* __restrict__ x)
{
    __shared__ int h[NB];
    int tid = threadIdx.x;
    h[tid] = 0;
    __syncthreads();
    int gid = blockIdx.x * 1024 + tid;
    atomicAdd(&h[bucket_of(x[gid])], 1);
    __syncthreads();
    if (h[tid]) atomicAdd(&g_hist[tid], h[tid]);
}

// ---------------------------------------------------------------------------
// K2: scan hist -> offsets; zero hist & cursor; compute GMM constants.
// 1 block x 1024 threads.
// ---------------------------------------------------------------------------
__global__ void __launch_bounds__(1024)
k_scan(const float* __restrict__ weight_logits,
       const float* __restrict__ means,
       const float* __restrict__ log_vars)
{
    __shared__ int sc_[NB];
    __shared__ float fb[64];
    int tid = threadIdx.x;

    sc_[tid] = g_hist[tid];
    g_hist[tid]   = 0;    // reset for next graph replay
    g_cursor[tid] = 0;
    __syncthreads();

    // Hillis-Steele inclusive scan over 1024
    #pragma unroll
    for (int off = 1; off < NB; off <<= 1) {
        int add = (tid >= off) ? sc_[tid - off] : 0;
        __syncthreads();
        sc_[tid] += add;
        __syncthreads();
    }
    if (tid == 0) g_off[0] = 0;
    g_off[tid + 1] = sc_[tid];

    // GMM constants: parallel softmax over 64 logits
    const float TWO_PI = 6.283185307179586f;
    float l = (tid < KK) ? weight_logits[tid] : 0.0f;
    if (tid < KK) fb[tid] = l;
    __syncthreads();
    if (tid < 32) fb[tid] = fmaxf(fb[tid], fb[tid + 32]); __syncthreads();
    if (tid < 16) fb[tid] = fmaxf(fb[tid], fb[tid + 16]); __syncthreads();
    if (tid <  8) fb[tid] = fmaxf(fb[tid], fb[tid +  8]); __syncthreads();
    if (tid <  4) fb[tid] = fmaxf(fb[tid], fb[tid +  4]); __syncthreads();
    if (tid <  2) fb[tid] = fmaxf(fb[tid], fb[tid +  2]); __syncthreads();
    if (tid <  1) fb[tid] = fmaxf(fb[tid], fb[tid +  1]); __syncthreads();
    float mx = fb[0];
    __syncthreads();
    float e = (tid < KK) ? expf(l - mx) : 0.0f;
    if (tid < KK) fb[tid] = e;
    __syncthreads();
    if (tid < 32) fb[tid] += fb[tid + 32]; __syncthreads();
    if (tid < 16) fb[tid] += fb[tid + 16]; __syncthreads();
    if (tid <  8) fb[tid] += fb[tid +  8]; __syncthreads();
    if (tid <  4) fb[tid] += fb[tid +  4]; __syncthreads();
    if (tid <  2) fb[tid] += fb[tid +  2]; __syncthreads();
    if (tid <  1) fb[tid] += fb[tid +  1]; __syncthreads();
    float invs = 1.0f / fb[0];

    if (tid < KK) {
        float w   = e * invs;
        float var = expf(log_vars[tid]);
        g_a[tid]  = w * rsqrtf(TWO_PI * var);
        g_c[tid]  = -0.5f / var;
        g_mu[tid] = means[tid];
    }
}

// ---------------------------------------------------------------------------
// K3: scatter into bucket-grouped array. 8 blocks x 1024 threads.
// (intra-bucket order nondeterministic here; canonicalized by K4 sort)
// ---------------------------------------------------------------------------
__global__ void __launch_bounds__(1024)
k_scatter(const float* __restrict__ x)
{
    int gid = blockIdx.x * 1024 + threadIdx.x;
    float v = x[gid];
    int b = bucket_of(v);
    int slot = g_off[b] + atomicAdd(&g_cursor[b], 1);
    g_sv[slot] = v;
}

// ---------------------------------------------------------------------------
// K4: sort each bucket by value (warp-per-bucket bitonic, pad 128 with +inf).
// 128 blocks x 256 threads (8 warps/block).
// ---------------------------------------------------------------------------
__global__ void __launch_bounds__(256)
k_sortbuckets()
{
    __shared__ float buf[8][128];
    int warp = threadIdx.x >> 5, lane = threadIdx.x & 31;
    int b = blockIdx.x * 8 + warp;
    int lo = g_off[b], hi = g_off[b + 1];
    int cnt = hi - lo;
    float* s = buf[warp];
    const float FINF = __int_as_float(0x7f800000);

    #pragma unroll
    for (int t = lane; t < 128; t += 32)
        s[t] = (t < cnt) ? g_sv[lo + t] : FINF;
    __syncwarp();

    for (int k = 2; k <= 128; k <<= 1) {
        for (int j = k >> 1; j > 0; j >>= 1) {
            #pragma unroll
            for (int t = lane; t < 128; t += 32) {
                int ixj = t ^ j;
                if (ixj > t) {
                    bool up = ((t & k) == 0);
                    float a = s[t], c = s[ixj];
                    if ((a > c) == up) { s[t] = c; s[ixj] = a; }
                }
            }
            __syncwarp();
        }
    }
    for (int t = lane; t < cnt; t += 32)
        g_sv[lo + t] = s[t];
}

// ---------------------------------------------------------------------------
// K5: windowed pairwise KDE + mixture pdf. 128 blocks x 64 threads.
// ---------------------------------------------------------------------------
__global__ void __launch_bounds__(64)
k_pair()
{
    __shared__ float sa[KK], sc[KK], smu[KK];
    int tid = threadIdx.x;
    sa[tid]  = g_a[tid];
    sc[tid]  = g_c[tid];
    smu[tid] = g_mu[tid];
    __syncthreads();

    int s = blockIdx.x * 64 + tid;
    float xi = g_sv[s];
    int b = bucket_of(xi);
    int jlo = g_off[max(b - RWIN, 0)];
    int jhi = g_off[min(b + RWIN + 1, NB)];

    float a0 = 0.f, a1 = 0.f, a2 = 0.f, a3 = 0.f;
    int j = jlo;
    for (; j + 4 <= jhi; j += 4) {
        float d0 = xi - __ldg(&g_sv[j + 0]);
        float d1 = xi - __ldg(&g_sv[j + 1]);
        float d2 = xi - __ldg(&g_sv[j + 2]);
        float d3 = xi - __ldg(&g_sv[j + 3]);
        a0 += __expf(NEG_HALF_INV_BW2 * d0 * d0);
        a1 += __expf(NEG_HALF_INV_BW2 * d1 * d1);
        a2 += __expf(NEG_HALF_INV_BW2 * d2 * d2);
        a3 += __expf(NEG_HALF_INV_BW2 * d3 * d3);
    }
    for (; j < jhi; ++j) {
        float d = xi - __ldg(&g_sv[j]);
        a0 += __expf(NEG_HALF_INV_BW2 * d * d);
    }
    float kde = (a0 + a1) + (a2 + a3);

    // 1 / (sqrt(2*pi)*bw*N)
    const float invZ = (float)(1.0 / (0.0078125 * 2.5066282746310002 * 8192.0));
    float data_pdf = kde * invZ;

    float mix = 0.0f;
    #pragma unroll 8
    for (int k = 0; k < KK; ++k) {
        float d = xi - smu[k];
        mix += sa[k] * __expf(sc[k] * d * d);
    }
    float diff = mix - data_pdf;
    g_diff[s] = diff * diff;
}

// ---------------------------------------------------------------------------
// K6: final deterministic sum. 1 block x 1024 threads.
// ---------------------------------------------------------------------------
__global__ void __launch_bounds__(1024)
k_reduce(float* __restrict__ out)
{
    __shared__ float red[1024];
    int tid = threadIdx.x;
    float acc = 0.0f;
    #pragma unroll
    for (int t = 0; t < NN / 1024; ++t)
        acc += g_diff[t * 1024 + tid];
    red[tid] = acc;
    __syncthreads();
    #pragma unroll
    for (int off = 512; off > 0; off >>= 1) {
        if (tid < off) red[tid] += red[tid + off];
        __syncthreads();
    }
    if (tid == 0) out[0] = red[0];
}

// ---------------------------------------------------------------------------
extern "C" void kernel_launch(void* const* d_in, const int* in_sizes, int n_in,
                              void* d_out, int out_size)
{
    const float* x             = (const float*)d_in[0];
    const float* weight_logits = (const float*)d_in[1];
    const float* means         = (const float*)d_in[2];
    const float* log_vars      = (const float*)d_in[3];
    float* out = (float*)d_out;

    k_hist<<<8, 1024>>>(x);
    k_scan<<<1, 1024>>>(weight_logits, means, log_vars);
    k_scatter<<<8, 1024>>>(x);
    k_sortbuckets<<<128, 256>>>();
    k_pair<<<128, 64>>>();
    k_reduce<<<1, 1024>>>(out);
}

// round 4
// speedup vs baseline: 1.0391x; 1.0391x over previous
#include <cuda_runtime.h>
#include <cuda_bf16.h>
#include <math.h>

// Problem constants
#define NN 8192
#define KK 64
#define NB 1024
#define XLO (-6.0f)
#define BW_INV (1024.0f / 12.0f)   // 1/bucket_width = 85.3333
#define RWIN 10                    // excluded pairs have |d| >= 10*w = 0.1172 -> exp == 0.0f exactly

#define NEG_HALF_INV_BW2 (-8192.0f)
#define PAIR_BLOCKS 64

// Scratch
__device__ int   g_off[NB + 1];
__device__ float g_tmp[NN];        // bucket-grouped (atomic order)
__device__ float g_sv[NN];         // bucket-grouped + value-sorted => globally sorted
__device__ float g_a[KK], g_c[KK], g_mu[KK];
__device__ float g_part[PAIR_BLOCKS];
__device__ int   g_counter;

__device__ __forceinline__ int bucket_of(float v) {
    int b = (int)floorf((v - XLO) * BW_INV);
    return min(max(b, 0), NB - 1);
}

// ---------------------------------------------------------------------------
// K1: hist + scan + scatter + GMM constants. 1 block x 1024 threads.
// ---------------------------------------------------------------------------
__global__ void __launch_bounds__(1024)
k_prep(const float* __restrict__ x,
       const float* __restrict__ weight_logits,
       const float* __restrict__ means,
       const float* __restrict__ log_vars)
{
    __shared__ int h[NB];
    __shared__ int scur[NB];

    const int tid = threadIdx.x;

    // keep this thread's 8 elements in registers
    float v[8]; int vb[8];
    #pragma unroll
    for (int k = 0; k < 8; ++k) {
        v[k]  = x[tid + k * 1024];
        vb[k] = bucket_of(v[k]);
    }

    h[tid] = 0;
    if (tid == 0) g_counter = 0;     // reset for k_pair's last-block pattern
    __syncthreads();

    #pragma unroll
    for (int k = 0; k < 8; ++k) atomicAdd(&h[vb[k]], 1);

    // GMM constants: warp 0 only, shuffle-based (no block syncs needed)
    if (tid < 32) {
        const float TWO_PI = 6.283185307179586f;
        float l0 = weight_logits[tid], l1 = weight_logits[tid + 32];
        float m = fmaxf(l0, l1);
        #pragma unroll
        for (int o = 16; o > 0; o >>= 1) m = fmaxf(m, __shfl_xor_sync(0xffffffffu, m, o));
        float e0 = expf(l0 - m), e1 = expf(l1 - m);
        float s = e0 + e1;
        #pragma unroll
        for (int o = 16; o > 0; o >>= 1) s += __shfl_xor_sync(0xffffffffu, s, o);
        float invs = 1.0f / s;

        float var0 = expf(log_vars[tid]);
        g_a[tid]  = e0 * invs * rsqrtf(TWO_PI * var0);
        g_c[tid]  = -0.5f / var0;
        g_mu[tid] = means[tid];

        float var1 = expf(log_vars[tid + 32]);
        g_a[tid + 32]  = e1 * invs * rsqrtf(TWO_PI * var1);
        g_c[tid + 32]  = -0.5f / var1;
        g_mu[tid + 32] = means[tid + 32];
    }
    __syncthreads();

    int mycnt = h[tid];
    __syncthreads();

    // Hillis-Steele inclusive scan over 1024
    #pragma unroll
    for (int off = 1; off < NB; off <<= 1) {
        int add = (tid >= off) ? h[tid - off] : 0;
        __syncthreads();
        h[tid] += add;
        __syncthreads();
    }
    if (tid == 0) g_off[0] = 0;
    g_off[tid + 1] = h[tid];
    scur[tid] = h[tid] - mycnt;      // exclusive offset = cursor start
    __syncthreads();

    // scatter (intra-bucket order nondeterministic; canonicalized by k_sort)
    #pragma unroll
    for (int k = 0; k < 8; ++k) {
        int slot = atomicAdd(&scur[vb[k]], 1);
        g_tmp[slot] = v[k];
    }
}

// ---------------------------------------------------------------------------
// K2: rank-sort each bucket by value (warp per bucket). Equal values are
// interchangeable, so the result is canonical -> deterministic.
// 128 blocks x 256 threads (8 warps).
// ---------------------------------------------------------------------------
__global__ void __launch_bounds__(256)
k_sort()
{
    __shared__ float buf[8][128];
    const int warp = threadIdx.x >> 5, lane = threadIdx.x & 31;
    const int b  = blockIdx.x * 8 + warp;
    const int lo = g_off[b];
    int cnt = g_off[b + 1] - lo;
    if (cnt > 128) cnt = 128;        // never happens for this data; safety
    float* s = buf[warp];

    for (int t = lane; t < cnt; t += 32) s[t] = g_tmp[lo + t];
    __syncwarp();

    for (int t = lane; t < cnt; t += 32) {
        float val = s[t];
        int rank = 0;
        for (int u = 0; u < cnt; ++u) {
            float o = s[u];
            rank += (o < val) || (o == val && u < t);
        }
        g_sv[lo + rank] = val;
    }
}

// ---------------------------------------------------------------------------
// K3: windowed KDE + mixture + fused deterministic reduction.
// 64 blocks x 128 threads. Warp w of block b handles sorted chunk b + 64*w
// (stratified assignment -> balanced block work).
// ---------------------------------------------------------------------------
__global__ void __launch_bounds__(128)
k_pair(float* __restrict__ out)
{
    __shared__ float sa[KK], sc[KK], smu[KK];
    __shared__ float red[128];
    __shared__ int slast;

    const int tid  = threadIdx.x;
    const int warp = tid >> 5, lane = tid & 31;

    if (tid < KK) { sa[tid] = g_a[tid]; sc[tid] = g_c[tid]; smu[tid] = g_mu[tid]; }
    __syncthreads();

    const int chunk = blockIdx.x + PAIR_BLOCKS * warp;   // 0..255
    const int i = chunk * 32 + lane;

    float xi = g_sv[i];
    int b = bucket_of(xi);
    int jlo = g_off[max(b - RWIN, 0)];
    int jhi = g_off[min(b + RWIN + 1, NB)];

    float a0 = 0.f, a1 = 0.f, a2 = 0.f, a3 = 0.f;
    int j = jlo;
    for (; j + 4 <= jhi; j += 4) {
        float d0 = xi - g_sv[j + 0];
        float d1 = xi - g_sv[j + 1];
        float d2 = xi - g_sv[j + 2];
        float d3 = xi - g_sv[j + 3];
        a0 += __expf(NEG_HALF_INV_BW2 * d0 * d0);
        a1 += __expf(NEG_HALF_INV_BW2 * d1 * d1);
        a2 += __expf(NEG_HALF_INV_BW2 * d2 * d2);
        a3 += __expf(NEG_HALF_INV_BW2 * d3 * d3);
    }
    for (; j < jhi; ++j) {
        float d = xi - g_sv[j];
        a0 += __expf(NEG_HALF_INV_BW2 * d * d);
    }
    float kde = (a0 + a1) + (a2 + a3);

    const float invZ = (float)(1.0 / (0.0078125 * 2.5066282746310002 * 8192.0));
    float data_pdf = kde * invZ;

    float mix = 0.0f;
    #pragma unroll 8
    for (int k = 0; k < KK; ++k) {
        float d = xi - smu[k];
        mix += sa[k] * __expf(sc[k] * d * d);
    }
    float diff = mix - data_pdf;

    // block reduction (deterministic tree)
    red[tid] = diff * diff;
    __syncthreads();
    #pragma unroll
    for (int off = 64; off > 0; off >>= 1) {
        if (tid < off) red[tid] += red[tid + off];
        __syncthreads();
    }

    if (tid == 0) {
        g_part[blockIdx.x] = red[0];
        __threadfence();
        int old = atomicAdd(&g_counter, 1);
        slast = (old == PAIR_BLOCKS - 1);
    }
    __syncthreads();

    // last block sums the 64 partials in a fixed order
    if (slast && tid < 32) {
        __threadfence();
        volatile float* vp = g_part;
        float s = vp[lane] + vp[lane + 32];
        #pragma unroll
        for (int o = 16; o > 0; o >>= 1) s += __shfl_xor_sync(0xffffffffu, s, o);
        if (lane == 0) out[0] = s;
    }
}

// ---------------------------------------------------------------------------
extern "C" void kernel_launch(void* const* d_in, const int* in_sizes, int n_in,
                              void* d_out, int out_size)
{
    const float* x             = (const float*)d_in[0];
    const float* weight_logits = (const float*)d_in[1];
    const float* means         = (const float*)d_in[2];
    const float* log_vars      = (const float*)d_in[3];
    float* out = (float*)d_out;

    k_prep<<<1, 1024>>>(x, weight_logits, means, log_vars);
    k_sort<<<128, 256>>>();
    k_pair<<<PAIR_BLOCKS, 128>>>(out);
}

// round 7
// speedup vs baseline: 1.7547x; 1.6887x over previous
#include <cuda_runtime.h>
#include <cuda_bf16.h>
#include <math.h>

// Problem constants
#define NN 8192
#define KK 64
#define NB 1024
#define XLO (-6.0f)
#define BW_INVF (1024.0f / 12.0f)   // 1/bucket_width
#define RWIN 10                     // excluded pairs: |d| > 10*w = 0.1172 -> exp == 0.0f exactly
#define CEXP (-8192.0f)             // -0.5/bw^2
#define GRID 128
#define TPB 128

// Persistent scratch
__device__ int   g_bar;             // monotonic barrier counter (never reset)
__device__ int   g_hist[NB];        // zero at entry (re-zeroed in P4 for next call)
__device__ int   g_cursor[NB];      // zeroed in P1
__device__ float g_tmp[NN];         // bucket-grouped (atomic order)
__device__ float g_sv[NN];          // globally value-sorted
__device__ float g_a[KK], g_c[KK], g_mu[KK];
__device__ float g_part[GRID];

__device__ __forceinline__ int bucket_of(float v) {
    int b = (int)floorf((v - XLO) * BW_INVF);
    return min(max(b, 0), NB - 1);
}

// Software global barrier: monotonic counter, works across graph replays.
__device__ __forceinline__ void gbar() {
    __syncthreads();
    if (threadIdx.x == 0) {
        __threadfence();
        int tok = atomicAdd(&g_bar, 1);
        int target = (tok & ~(GRID - 1)) + GRID;   // next multiple of GRID
        while (*((volatile int*)&g_bar) < target) { }
        __threadfence();
    }
    __syncthreads();
}

__global__ void __launch_bounds__(TPB, 1)
gmm_fused(const float* __restrict__ x,
          const float* __restrict__ weight_logits,
          const float* __restrict__ means,
          const float* __restrict__ log_vars,
          float* __restrict__ out)
{
    __shared__ int   soff[NB + 1];
    __shared__ __align__(16) float winbuf[4][1024];  // per-warp window buffer (16B-aligned for float4)
    __shared__ float sa[KK], sc[KK], smu[KK];
    __shared__ float khalf[2][2][32];          // [chunk-slot][window-half][lane]
    __shared__ float red[TPB];
    __shared__ int   wtot[4];

    const int tid  = threadIdx.x;
    const int blk  = blockIdx.x;
    const int lane = tid & 31;
    const int w    = tid >> 5;
    const unsigned FULL = 0xffffffffu;

    // ---------------- P1: histogram + cursor zero + GMM constants ----------
    float v = 0.0f; int vb = 0;
    if (tid < 64) {
        int gid = blk * 64 + tid;
        v  = x[gid];
        vb = bucket_of(v);
        atomicAdd(&g_hist[vb], 1);
    }
    {
        int zidx = blk * TPB + tid;
        if (zidx < NB) g_cursor[zidx] = 0;
    }
    if (blk == 0 && tid < 32) {
        const float TWO_PI = 6.283185307179586f;
        float l0 = weight_logits[tid], l1 = weight_logits[tid + 32];
        float m = fmaxf(l0, l1);
        #pragma unroll
        for (int o = 16; o > 0; o >>= 1) m = fmaxf(m, __shfl_xor_sync(FULL, m, o));
        float e0 = expf(l0 - m), e1 = expf(l1 - m);
        float s = e0 + e1;
        #pragma unroll
        for (int o = 16; o > 0; o >>= 1) s += __shfl_xor_sync(FULL, s, o);
        float invs = 1.0f / s;

        float var0 = expf(log_vars[tid]);
        g_a[tid]  = e0 * invs * rsqrtf(TWO_PI * var0);
        g_c[tid]  = -0.5f / var0;
        g_mu[tid] = means[tid];
        float var1 = expf(log_vars[tid + 32]);
        g_a[tid + 32]  = e1 * invs * rsqrtf(TWO_PI * var1);
        g_c[tid + 32]  = -0.5f / var1;
        g_mu[tid + 32] = means[tid + 32];
    }

    gbar();  // B1: hist complete, cursors zeroed, consts published

    // ---------------- P2: redundant per-block scan of g_hist ---------------
    if (tid < KK) { sa[tid] = g_a[tid]; sc[tid] = g_c[tid]; smu[tid] = g_mu[tid]; }
    {
        int base = tid * 8;
        int c0 = g_hist[base + 0], c1 = g_hist[base + 1];
        int c2 = g_hist[base + 2], c3 = g_hist[base + 3];
        int c4 = g_hist[base + 4], c5 = g_hist[base + 5];
        int c6 = g_hist[base + 6], c7 = g_hist[base + 7];
        int tot = ((c0 + c1) + (c2 + c3)) + ((c4 + c5) + (c6 + c7));

        int incl = tot;
        #pragma unroll
        for (int o = 1; o < 32; o <<= 1) {
            int n = __shfl_up_sync(FULL, incl, o);
            if (lane >= o) incl += n;
        }
        if (lane == 31) wtot[w] = incl;
        __syncthreads();
        int wpre = 0;
        #pragma unroll
        for (int q = 0; q < 4; ++q) if (q < w) wpre += wtot[q];
        int run = wpre + incl - tot;    // exclusive prefix of this 8-bin chunk

        soff[base + 0] = run; run += c0;
        soff[base + 1] = run; run += c1;
        soff[base + 2] = run; run += c2;
        soff[base + 3] = run; run += c3;
        soff[base + 4] = run; run += c4;
        soff[base + 5] = run; run += c5;
        soff[base + 6] = run; run += c6;
        soff[base + 7] = run; run += c7;
        if (tid == TPB - 1) soff[NB] = run;   // == NN
    }
    __syncthreads();

    // ---------------- P3: scatter --------------------------------------
    if (tid < 64) {
        int slot = soff[vb] + atomicAdd(&g_cursor[vb], 1);
        g_tmp[slot] = v;
    }

    gbar();  // B2: scatter complete

    // ---------------- P4: rank-sort 8 buckets per block; zero hist -----
    {
        int zidx = blk * TPB + tid;
        if (zidx < NB) g_hist[zidx] = 0;      // ready for next replay
    }
    {
        float* sbuf = winbuf[w];              // 1024 floats per warp, plenty
        #pragma unroll
        for (int q = 0; q < 2; ++q) {
            int b  = (blk * 4 + w) * 2 + q;
            int lo = soff[b];
            int cnt = soff[b + 1] - lo;
            for (int t = lane; t < cnt; t += 32) sbuf[t] = g_tmp[lo + t];
            __syncwarp();
            for (int t = lane; t < cnt; t += 32) {
                float val = sbuf[t];
                int rank = 0;
                for (int u = 0; u < cnt; ++u) {
                    float o = sbuf[u];
                    rank += (o < val) || (o == val && u < t);
                }
                g_sv[lo + rank] = val;
            }
            __syncwarp();
        }
    }

    gbar();  // B3: g_sv sorted & complete

    // ---------------- P5: windowed KDE + mixture ------------------------
    // 256 chunks of 32 sorted elements. Block handles chunks blk, blk+128.
    // Each chunk gets 2 warps; each warp does alternating 1024-wide window pieces.
    {
        const int slot  = w >> 1;             // 0 or 1
        const int half  = w & 1;              // which interleaved piece set
        const int chunk = blk + GRID * slot;  // 0..255
        const int i     = chunk * 32 + lane;

        float xi = g_sv[i];
        float x0 = __shfl_sync(FULL, xi, 0);
        float x31 = __shfl_sync(FULL, xi, 31);
        int jlo = soff[max(bucket_of(x0) - RWIN, 0)];
        int jhi = soff[min(bucket_of(x31) + RWIN + 1, NB)];

        float* wbuf = winbuf[w];
        float a0 = 0.f, a1 = 0.f, a2 = 0.f, a3 = 0.f;

        for (int pos = jlo + half * 1024; pos < jhi; pos += 2048) {
            int cnt = min(1024, jhi - pos);
            for (int t = lane; t < cnt; t += 32) wbuf[t] = g_sv[pos + t];
            __syncwarp();
            int k = 0;
            for (; k + 4 <= cnt; k += 4) {
                float4 q = *(const float4*)&wbuf[k];
                float d0 = xi - q.x, d1 = xi - q.y, d2 = xi - q.z, d3 = xi - q.w;
                a0 += __expf(CEXP * d0 * d0);
                a1 += __expf(CEXP * d1 * d1);
                a2 += __expf(CEXP * d2 * d2);
                a3 += __expf(CEXP * d3 * d3);
            }
            for (; k < cnt; ++k) {
                float d = xi - wbuf[k];
                a0 += __expf(CEXP * d * d);
            }
            __syncwarp();
        }
        khalf[slot][half][lane] = (a0 + a1) + (a2 + a3);
    }
    __syncthreads();

    {
        float contrib = 0.0f;
        if ((w & 1) == 0) {
            const int slot  = w >> 1;
            const int chunk = blk + GRID * slot;
            const int i     = chunk * 32 + lane;
            float xi = g_sv[i];

            float kde = khalf[slot][0][lane] + khalf[slot][1][lane];
            const float invZ = (float)(1.0 / (0.0078125 * 2.5066282746310002 * 8192.0));
            float data_pdf = kde * invZ;

            float mix = 0.0f;
            #pragma unroll 8
            for (int k = 0; k < KK; ++k) {
                float d = xi - smu[k];
                mix += sa[k] * __expf(sc[k] * d * d);
            }
            float diff = mix - data_pdf;
            contrib = diff * diff;
        }
        red[tid] = contrib;
    }
    __syncthreads();
    #pragma unroll
    for (int off = TPB / 2; off > 0; off >>= 1) {
        if (tid < off) red[tid] += red[tid + off];
        __syncthreads();
    }
    if (tid == 0) g_part[blk] = red[0];

    gbar();  // B4: all partials written

    // ---------------- P6: final fixed-order reduction -------------------
    if (blk == 0) {
        red[tid] = g_part[tid];
        __syncthreads();
        #pragma unroll
        for (int off = TPB / 2; off > 0; off >>= 1) {
            if (tid < off) red[tid] += red[tid + off];
            __syncthreads();
        }
        if (tid == 0) out[0] = red[0];
    }
}

// ---------------------------------------------------------------------------
extern "C" void kernel_launch(void* const* d_in, const int* in_sizes, int n_in,
                              void* d_out, int out_size)
{
    const float* x             = (const float*)d_in[0];
    const float* weight_logits = (const float*)d_in[1];
    const float* means         = (const float*)d_in[2];
    const float* log_vars      = (const float*)d_in[3];
    float* out = (float*)d_out;

    gmm_fused<<<GRID, TPB>>>(x, weight_logits, means, log_vars, out);
}

// round 8
// speedup vs baseline: 1.8907x; 1.0775x over previous
#include <cuda_runtime.h>
#include <cuda_bf16.h>
#include <math.h>

// Problem constants
#define NN 8192
#define KK 64
#define NB 1024
#define XLO (-6.0f)
#define BW_INVF (1024.0f / 12.0f)   // 1/bucket_width
#define RWIN 10                     // excluded pairs: |d| > 10*w = 0.1172 -> __expf == 0.0f exactly
#define CEXP (-8192.0f)             // -0.5/bw^2
#define GRID 128
#define TPB 256
#define BCAP 512                    // per-bucket capacity (N(0,1) peak bucket ~40)

// Persistent scratch (monotonic counters survive graph replays; no resets needed)
__device__ int   g_bar;             // global barrier counter
__device__ int   g_cnt;             // last-block counter
__device__ float g_sv[NN];          // globally value-sorted x (fully rewritten each call)
__device__ float g_a[KK], g_c[KK], g_mu[KK];
__device__ float g_part[GRID];

__device__ __forceinline__ int bucket_of(float v) {
    int b = (int)floorf((v - XLO) * BW_INVF);
    return min(max(b, 0), NB - 1);
}

// Software global barrier: monotonic counter, graph-replay safe.
__device__ __forceinline__ void gbar() {
    __syncthreads();
    if (threadIdx.x == 0) {
        __threadfence();
        int tok = atomicAdd(&g_bar, 1);
        int target = (tok & ~(GRID - 1)) + GRID;   // next multiple of GRID
        while (*((volatile int*)&g_bar) < target) { }
        __threadfence();
    }
    __syncthreads();
}

__global__ void __launch_bounds__(TPB, 1)
gmm_fused(const float* __restrict__ x,
          const float* __restrict__ weight_logits,
          const float* __restrict__ means,
          const float* __restrict__ log_vars,
          float* __restrict__ out)
{
    __shared__ int   hist[NB];
    __shared__ int   soff[NB + 1];
    __shared__ float sbuck[8][BCAP];
    __shared__ int   cur[8];
    __shared__ float sa[KK], sc[KK], smu[KK];
    __shared__ float kq[2][4][32];      // [chunk-slot][quarter][lane]
    __shared__ float rpair[2];
    __shared__ float fred[GRID];
    __shared__ int   wtot[8];
    __shared__ int   slast;

    const int tid  = threadIdx.x;
    const int blk  = blockIdx.x;
    const int lane = tid & 31;
    const int w    = tid >> 5;
    const unsigned FULL = 0xffffffffu;

    // ---- GMM constants (block 0, warp 0 only; published via gbar fence) ----
    if (blk == 0 && tid < 32) {
        const float TWO_PI = 6.283185307179586f;
        float l0 = weight_logits[tid], l1 = weight_logits[tid + 32];
        float m = fmaxf(l0, l1);
        #pragma unroll
        for (int o = 16; o > 0; o >>= 1) m = fmaxf(m, __shfl_xor_sync(FULL, m, o));
        float e0 = expf(l0 - m), e1 = expf(l1 - m);
        float s = e0 + e1;
        #pragma unroll
        for (int o = 16; o > 0; o >>= 1) s += __shfl_xor_sync(FULL, s, o);
        float invs = 1.0f / s;

        float var0 = expf(log_vars[tid]);
        g_a[tid]  = e0 * invs * rsqrtf(TWO_PI * var0);
        g_c[tid]  = -0.5f / var0;
        g_mu[tid] = means[tid];
        float var1 = expf(log_vars[tid + 32]);
        g_a[tid + 32]  = e1 * invs * rsqrtf(TWO_PI * var1);
        g_c[tid + 32]  = -0.5f / var1;
        g_mu[tid + 32] = means[tid + 32];
    }

    // ---- P1: block-private histogram over ALL of x (redundant, no barrier) ----
    #pragma unroll
    for (int q = 0; q < NB / TPB; ++q) hist[q * TPB + tid] = 0;
    if (tid < 8) cur[tid] = 0;
    __syncthreads();

    #pragma unroll 8
    for (int t = 0; t < NN / TPB; ++t) {
        float v = x[t * TPB + tid];
        atomicAdd(&hist[bucket_of(v)], 1);
    }
    __syncthreads();

    // ---- P2: redundant scan (4 bins/thread, warp scan + cross-warp fixup) ----
    {
        int base = tid * 4;
        int c0 = hist[base + 0], c1 = hist[base + 1];
        int c2 = hist[base + 2], c3 = hist[base + 3];
        int tot = (c0 + c1) + (c2 + c3);

        int incl = tot;
        #pragma unroll
        for (int o = 1; o < 32; o <<= 1) {
            int n = __shfl_up_sync(FULL, incl, o);
            if (lane >= o) incl += n;
        }
        if (lane == 31) wtot[w] = incl;
        __syncthreads();
        int wpre = 0;
        #pragma unroll
        for (int q = 0; q < 8; ++q) if (q < w) wpre += wtot[q];
        int run = wpre + incl - tot;

        soff[base + 0] = run; run += c0;
        soff[base + 1] = run; run += c1;
        soff[base + 2] = run; run += c2;
        soff[base + 3] = run; run += c3;
        if (tid == TPB - 1) soff[NB] = run;   // == NN
    }
    __syncthreads();

    // ---- P3: select this block's 8 buckets directly from x (L1-hot reread) ----
    const int b0 = blk * 8;
    #pragma unroll 8
    for (int t = 0; t < NN / TPB; ++t) {
        float v = x[t * TPB + tid];
        unsigned lb = (unsigned)(bucket_of(v) - b0);
        if (lb < 8u) {
            int p = atomicAdd(&cur[lb], 1);
            if (p < BCAP) sbuck[lb][p] = v;
        }
    }
    __syncthreads();

    // ---- P4: rank-sort bucket w (canonical by value -> deterministic) ----
    {
        int b  = b0 + w;
        int lo = soff[b];
        int cnt = soff[b + 1] - lo;
        if (cnt > BCAP) cnt = BCAP;
        for (int t = lane; t < cnt; t += 32) {
            float val = sbuck[w][t];
            int rank = 0;
            for (int u = 0; u < cnt; ++u) {
                float o = sbuck[w][u];
                rank += (o < val) || (o == val && u < t);
            }
            g_sv[lo + rank] = val;
        }
    }

    gbar();  // the ONLY global barrier: g_sv + constants published

    if (tid < KK) { sa[tid] = g_a[tid]; sc[tid] = g_c[tid]; smu[tid] = g_mu[tid]; }

    // ---- P5: windowed KDE. 256 chunks of 32 sorted elems; block handles
    // chunks blk and blk+128; 4 warps per chunk take contiguous quarter-windows.
    // Window bounds aligned to x4: extra elements are > RWIN*w away -> exp == 0.0f.
    {
        const int slot  = w >> 2;            // 0/1 -> chunk A/B
        const int q4    = w & 3;             // quarter
        const int chunk = blk + GRID * slot; // 0..255
        const int i     = chunk * 32 + lane;

        float xi  = g_sv[i];
        float x0  = __shfl_sync(FULL, xi, 0);
        float x31 = __shfl_sync(FULL, xi, 31);
        int jlo = soff[max(bucket_of(x0)  - RWIN,     0)] & ~3;
        int jhi = (soff[min(bucket_of(x31) + RWIN + 1, NB)] + 3) & ~3;   // <= NN
        int len  = jhi - jlo;                       // multiple of 4
        int qlen = (((len >> 2) + 3) & ~3);         // quarter length, multiple of 4
        int qs = jlo + q4 * qlen;
        int qe = min(qs + qlen, jhi);

        float a0 = 0.f, a1 = 0.f, a2 = 0.f, a3 = 0.f;
        for (int k = qs; k < qe; k += 4) {
            float4 qv = *(const float4*)&g_sv[k];   // warp-uniform broadcast, L1-hot
            float d0 = xi - qv.x, d1 = xi - qv.y, d2 = xi - qv.z, d3 = xi - qv.w;
            a0 += __expf(CEXP * d0 * d0);
            a1 += __expf(CEXP * d1 * d1);
            a2 += __expf(CEXP * d2 * d2);
            a3 += __expf(CEXP * d3 * d3);
        }
        kq[slot][q4][lane] = (a0 + a1) + (a2 + a3);
    }
    __syncthreads();

    // quarter combine + mixture + per-chunk warp reduction (warps 0 and 4)
    if ((w & 3) == 0) {
        const int slot  = w >> 2;
        const int chunk = blk + GRID * slot;
        const int i     = chunk * 32 + lane;
        float xi = g_sv[i];

        float kde = (kq[slot][0][lane] + kq[slot][1][lane])
                  + (kq[slot][2][lane] + kq[slot][3][lane]);
        const float invZ = (float)(1.0 / (0.0078125 * 2.5066282746310002 * 8192.0));
        float data_pdf = kde * invZ;

        float mix = 0.0f;
        #pragma unroll 8
        for (int k = 0; k < KK; ++k) {
            float d = xi - smu[k];
            mix += sa[k] * __expf(sc[k] * d * d);
        }
        float diff = mix - data_pdf;
        float dd = diff * diff;
        #pragma unroll
        for (int o = 16; o > 0; o >>= 1) dd += __shfl_xor_sync(FULL, dd, o);
        if (lane == 0) rpair[slot] = dd;
    }
    __syncthreads();

    // ---- P6: publish partial; last block does fixed-order final sum ----
    if (tid == 0) {
        g_part[blk] = rpair[0] + rpair[1];
        __threadfence();
        int old = atomicAdd(&g_cnt, 1);
        slast = (((old + 1) & (GRID - 1)) == 0);
    }
    __syncthreads();

    if (slast) {
        if (tid < GRID) {
            volatile float* vp = g_part;    // bypass L1 (written by other SMs)
            fred[tid] = vp[tid];
        }
        __syncthreads();
        #pragma unroll
        for (int off = GRID / 2; off > 0; off >>= 1) {
            if (tid < off) fred[tid] += fred[tid + off];
            __syncthreads();
        }
        if (tid == 0) out[0] = fred[0];
    }
}

// ---------------------------------------------------------------------------
extern "C" void kernel_launch(void* const* d_in, const int* in_sizes, int n_in,
                              void* d_out, int out_size)
{
    const float* x             = (const float*)d_in[0];
    const float* weight_logits = (const float*)d_in[1];
    const float* means         = (const float*)d_in[2];
    const float* log_vars      = (const float*)d_in[3];
    float* out = (float*)d_out;

    gmm_fused<<<GRID, TPB>>>(x, weight_logits, means, log_vars, out);
}

// round 9
// speedup vs baseline: 2.0468x; 1.0825x over previous
#include <cuda_runtime.h>
#include <cuda_bf16.h>
#include <math.h>

// Problem constants
#define NN 8192
#define KK 64
#define NB 1024
#define XLO (-6.0f)
#define BW_INVF (1024.0f / 12.0f)   // 1/bucket_width
#define RWIN 10                     // excluded pairs: |d| > 10*w = 0.1172 -> __expf == 0.0f exactly
#define CEXP (-8192.0f)             // -0.5/bw^2
#define GRID 128
#define TPB 256
#define BCAP 512                    // per-bucket capacity (N(0,1) peak bucket ~40)

// Persistent scratch (monotonic counters survive graph replays)
__device__ int   g_bar;             // global barrier counter
__device__ int   g_cnt;             // last-block counter
__device__ int   g_hist[NB];        // distributed histogram; zeroed after gbar2 each call
__device__ float g_sv[NN];          // globally value-sorted x (fully rewritten each call)
__device__ float g_a[KK], g_c[KK], g_mu[KK];
__device__ float g_part[GRID];

__device__ __forceinline__ int bucket_of(float v) {
    int b = (int)floorf((v - XLO) * BW_INVF);
    return min(max(b, 0), NB - 1);
}

// Software global barrier: monotonic counter, graph-replay safe.
__device__ __forceinline__ void gbar() {
    __syncthreads();
    if (threadIdx.x == 0) {
        __threadfence();
        int tok = atomicAdd(&g_bar, 1);
        int target = (tok & ~(GRID - 1)) + GRID;   // next multiple of GRID
        while (*((volatile int*)&g_bar) < target) { }
        __threadfence();
    }
    __syncthreads();
}

__global__ void __launch_bounds__(TPB, 1)
gmm_fused(const float* __restrict__ x,
          const float* __restrict__ weight_logits,
          const float* __restrict__ means,
          const float* __restrict__ log_vars,
          float* __restrict__ out)
{
    __shared__ int   soff[NB + 1];
    __shared__ float sbuck[8][BCAP];
    __shared__ int   cur[8];
    __shared__ float sa[KK], sc[KK], smu[KK];
    __shared__ float kq[2][4][32];      // [chunk-slot][quarter][lane]
    __shared__ float rpair[2];
    __shared__ float fred[GRID];
    __shared__ int   wtot[8];
    __shared__ int   slast;

    const int tid  = threadIdx.x;
    const int blk  = blockIdx.x;
    const int lane = tid & 31;
    const int w    = tid >> 5;
    const unsigned FULL = 0xffffffffu;

    // ---- P1: distributed histogram (64 elems/block -> global red.add) ----
    if (tid < 64) {
        float v = x[blk * 64 + tid];
        atomicAdd(&g_hist[bucket_of(v)], 1);
    }
    if (tid < 8) cur[tid] = 0;

    // GMM constants (block 0, warp 0; published by gbar1's fence)
    if (blk == 0 && tid < 32) {
        const float TWO_PI = 6.283185307179586f;
        float l0 = weight_logits[tid], l1 = weight_logits[tid + 32];
        float m = fmaxf(l0, l1);
        #pragma unroll
        for (int o = 16; o > 0; o >>= 1) m = fmaxf(m, __shfl_xor_sync(FULL, m, o));
        float e0 = expf(l0 - m), e1 = expf(l1 - m);
        float s = e0 + e1;
        #pragma unroll
        for (int o = 16; o > 0; o >>= 1) s += __shfl_xor_sync(FULL, s, o);
        float invs = 1.0f / s;

        float var0 = expf(log_vars[tid]);
        g_a[tid]  = e0 * invs * rsqrtf(TWO_PI * var0);
        g_c[tid]  = -0.5f / var0;
        g_mu[tid] = means[tid];
        float var1 = expf(log_vars[tid + 32]);
        g_a[tid + 32]  = e1 * invs * rsqrtf(TWO_PI * var1);
        g_c[tid + 32]  = -0.5f / var1;
        g_mu[tid + 32] = means[tid + 32];
    }

    gbar();  // B1: histogram + constants published

    if (tid < KK) { sa[tid] = g_a[tid]; sc[tid] = g_c[tid]; smu[tid] = g_mu[tid]; }

    // ---- P2: redundant per-block scan of global hist (4 bins/thread) ----
    {
        int base = tid * 4;
        int c0 = g_hist[base + 0], c1 = g_hist[base + 1];
        int c2 = g_hist[base + 2], c3 = g_hist[base + 3];
        int tot = (c0 + c1) + (c2 + c3);

        int incl = tot;
        #pragma unroll
        for (int o = 1; o < 32; o <<= 1) {
            int n = __shfl_up_sync(FULL, incl, o);
            if (lane >= o) incl += n;
        }
        if (lane == 31) wtot[w] = incl;
        __syncthreads();
        int wpre = 0;
        #pragma unroll
        for (int q = 0; q < 8; ++q) if (q < w) wpre += wtot[q];
        int run = wpre + incl - tot;

        soff[base + 0] = run; run += c0;
        soff[base + 1] = run; run += c1;
        soff[base + 2] = run; run += c2;
        soff[base + 3] = run; run += c3;
        if (tid == TPB - 1) soff[NB] = run;   // == NN
    }
    __syncthreads();

    // ---- P3: select this block's 8 buckets from x (few smem atomics) ----
    const int b0 = blk * 8;
    #pragma unroll 8
    for (int t = 0; t < NN / TPB; ++t) {
        float v = x[t * TPB + tid];
        unsigned lb = (unsigned)(bucket_of(v) - b0);
        if (lb < 8u) {
            int p = atomicAdd(&cur[lb], 1);
            if (p < BCAP) sbuck[lb][p] = v;
        }
    }
    __syncthreads();

    // ---- P4: rank-sort bucket w (canonical by value -> deterministic) ----
    {
        int b  = b0 + w;
        int lo = soff[b];
        int cnt = soff[b + 1] - lo;
        if (cnt > BCAP) cnt = BCAP;
        for (int t = lane; t < cnt; t += 32) {
            float val = sbuck[w][t];
            int rank = 0;
            for (int u = 0; u < cnt; ++u) {
                float o = sbuck[w][u];
                rank += (o < val) || (o == val && u < t);
            }
            g_sv[lo + rank] = val;
        }
    }

    gbar();  // B2: g_sv published; all g_hist reads done

    // reset histogram for the next graph replay (race-free after B2)
    if (tid < 8) g_hist[b0 + tid] = 0;

    // ---- P5: windowed KDE. 256 chunks of 32 sorted elems; block handles
    // chunks blk and blk+128; 4 warps per chunk take contiguous quarter-windows.
    // Window bounds aligned to x4: extra elements are > RWIN*w away -> exp == 0.0f.
    {
        const int slot  = w >> 2;            // 0/1 -> chunk A/B
        const int q4    = w & 3;             // quarter
        const int chunk = blk + GRID * slot; // 0..255
        const int i     = chunk * 32 + lane;

        float xi  = g_sv[i];
        float x0  = __shfl_sync(FULL, xi, 0);
        float x31 = __shfl_sync(FULL, xi, 31);
        int jlo = soff[max(bucket_of(x0)  - RWIN,     0)] & ~3;
        int jhi = (soff[min(bucket_of(x31) + RWIN + 1, NB)] + 3) & ~3;   // <= NN
        int len  = jhi - jlo;                       // multiple of 4
        int qlen = (((len >> 2) + 3) & ~3);         // quarter length, multiple of 4
        int qs = jlo + q4 * qlen;
        int qe = min(qs + qlen, jhi);

        float a0 = 0.f, a1 = 0.f, a2 = 0.f, a3 = 0.f;
        for (int k = qs; k < qe; k += 4) {
            float4 qv = *(const float4*)&g_sv[k];   // warp-uniform broadcast, L1-hot
            float d0 = xi - qv.x, d1 = xi - qv.y, d2 = xi - qv.z, d3 = xi - qv.w;
            a0 += __expf(CEXP * d0 * d0);
            a1 += __expf(CEXP * d1 * d1);
            a2 += __expf(CEXP * d2 * d2);
            a3 += __expf(CEXP * d3 * d3);
        }
        kq[slot][q4][lane] = (a0 + a1) + (a2 + a3);
    }
    __syncthreads();

    // quarter combine + mixture + per-chunk warp reduction (warps 0 and 4)
    if ((w & 3) == 0) {
        const int slot  = w >> 2;
        const int chunk = blk + GRID * slot;
        const int i     = chunk * 32 + lane;
        float xi = g_sv[i];

        float kde = (kq[slot][0][lane] + kq[slot][1][lane])
                  + (kq[slot][2][lane] + kq[slot][3][lane]);
        const float invZ = (float)(1.0 / (0.0078125 * 2.5066282746310002 * 8192.0));
        float data_pdf = kde * invZ;

        float mix = 0.0f;
        #pragma unroll 8
        for (int k = 0; k < KK; ++k) {
            float d = xi - smu[k];
            mix += sa[k] * __expf(sc[k] * d * d);
        }
        float diff = mix - data_pdf;
        float dd = diff * diff;
        #pragma unroll
        for (int o = 16; o > 0; o >>= 1) dd += __shfl_xor_sync(FULL, dd, o);
        if (lane == 0) rpair[slot] = dd;
    }
    __syncthreads();

    // ---- P6: publish partial; last block does fixed-order final sum ----
    if (tid == 0) {
        g_part[blk] = rpair[0] + rpair[1];
        __threadfence();
        int old = atomicAdd(&g_cnt, 1);
        slast = (((old + 1) & (GRID - 1)) == 0);
    }
    __syncthreads();

    if (slast) {
        if (tid < GRID) {
            volatile float* vp = g_part;    // bypass L1 (written by other SMs)
            fred[tid] = vp[tid];
        }
        __syncthreads();
        #pragma unroll
        for (int off = GRID / 2; off > 0; off >>= 1) {
            if (tid < off) fred[tid] += fred[tid + off];
            __syncthreads();
        }
        if (tid == 0) out[0] = fred[0];
    }
}

// ---------------------------------------------------------------------------
extern "C" void kernel_launch(void* const* d_in, const int* in_sizes, int n_in,
                              void* d_out, int out_size)
{
    const float* x             = (const float*)d_in[0];
    const float* weight_logits = (const float*)d_in[1];
    const float* means         = (const float*)d_in[2];
    const float* log_vars      = (const float*)d_in[3];
    float* out = (float*)d_out;

    gmm_fused<<<GRID, TPB>>>(x, weight_logits, means, log_vars, out);
}

// round 10
// speedup vs baseline: 2.5655x; 1.2534x over previous
#include <cuda_runtime.h>
#include <cuda_bf16.h>
#include <math.h>

// Problem constants
#define NN 8192
#define KK 64
#define NB 1024
#define XLO (-6.0f)
#define BW_INVF (1024.0f / 12.0f)   // 1/bucket_width
#define RWIN 10                     // excluded pairs: |d| > 10*w = 0.1172 -> __expf == 0.0f exactly
#define CEXP (-8192.0f)             // -0.5/bw^2
#define GRID 128
#define TPB 512
#define BCAP 512                    // per-bucket capacity (N(0,1) peak bucket ~40)
#define WBUF 192                    // per-warp staged window-eighth capacity (worst ~135)

// Persistent scratch (monotonic counters survive graph replays)
__device__ int   g_bar;             // global barrier counter
__device__ int   g_cnt;             // last-block counter
__device__ int   g_hist[NB];        // distributed histogram; zeroed after gbar2 each call
__device__ float g_sv[NN];          // globally value-sorted x (fully rewritten each call)
__device__ float g_a[KK], g_c[KK], g_mu[KK];
__device__ float g_part[GRID];

__device__ __forceinline__ int bucket_of(float v) {
    int b = (int)floorf((v - XLO) * BW_INVF);
    return min(max(b, 0), NB - 1);
}

// Software global barrier: monotonic counter, graph-replay safe.
__device__ __forceinline__ void gbar() {
    __syncthreads();
    if (threadIdx.x == 0) {
        __threadfence();
        int tok = atomicAdd(&g_bar, 1);
        int target = (tok & ~(GRID - 1)) + GRID;   // next multiple of GRID
        while (*((volatile int*)&g_bar) < target) { }
        __threadfence();
    }
    __syncthreads();
}

__global__ void __launch_bounds__(TPB, 1)
gmm_fused(const float* __restrict__ x,
          const float* __restrict__ weight_logits,
          const float* __restrict__ means,
          const float* __restrict__ log_vars,
          float* __restrict__ out)
{
    __shared__ int   soff[NB + 1];
    __shared__ float sbuck[8][BCAP];
    __shared__ int   cur[8];
    __shared__ float sa[KK], sc[KK], smu[KK];
    __shared__ __align__(16) float wb[16][WBUF];   // per-warp staged eighth-window
    __shared__ float kq[2][8][32];      // [chunk-slot][eighth][lane]
    __shared__ float rpair[2];
    __shared__ float fred[GRID];
    __shared__ int   wtot[16];
    __shared__ int   slast;

    const int tid  = threadIdx.x;
    const int blk  = blockIdx.x;
    const int lane = tid & 31;
    const int w    = tid >> 5;          // 0..15
    const unsigned FULL = 0xffffffffu;

    // ---- P1: distributed histogram (64 elems/block -> global red.add) ----
    if (tid < 64) {
        float v = x[blk * 64 + tid];
        atomicAdd(&g_hist[bucket_of(v)], 1);
    }
    if (tid < 8) cur[tid] = 0;

    // GMM constants (block 0, warp 0; published by gbar1's fence)
    if (blk == 0 && tid < 32) {
        const float TWO_PI = 6.283185307179586f;
        float l0 = weight_logits[tid], l1 = weight_logits[tid + 32];
        float m = fmaxf(l0, l1);
        #pragma unroll
        for (int o = 16; o > 0; o >>= 1) m = fmaxf(m, __shfl_xor_sync(FULL, m, o));
        float e0 = expf(l0 - m), e1 = expf(l1 - m);
        float s = e0 + e1;
        #pragma unroll
        for (int o = 16; o > 0; o >>= 1) s += __shfl_xor_sync(FULL, s, o);
        float invs = 1.0f / s;

        float var0 = expf(log_vars[tid]);
        g_a[tid]  = e0 * invs * rsqrtf(TWO_PI * var0);
        g_c[tid]  = -0.5f / var0;
        g_mu[tid] = means[tid];
        float var1 = expf(log_vars[tid + 32]);
        g_a[tid + 32]  = e1 * invs * rsqrtf(TWO_PI * var1);
        g_c[tid + 32]  = -0.5f / var1;
        g_mu[tid + 32] = means[tid + 32];
    }

    gbar();  // B1: histogram + constants published

    if (tid < KK) { sa[tid] = g_a[tid]; sc[tid] = g_c[tid]; smu[tid] = g_mu[tid]; }

    // ---- P2: redundant per-block scan of global hist (2 bins/thread) ----
    {
        int base = tid * 2;
        int c0 = g_hist[base + 0], c1 = g_hist[base + 1];
        int tot = c0 + c1;

        int incl = tot;
        #pragma unroll
        for (int o = 1; o < 32; o <<= 1) {
            int n = __shfl_up_sync(FULL, incl, o);
            if (lane >= o) incl += n;
        }
        if (lane == 31) wtot[w] = incl;
        __syncthreads();
        int wpre = 0;
        #pragma unroll
        for (int q = 0; q < 16; ++q) if (q < w) wpre += wtot[q];
        int run = wpre + incl - tot;

        soff[base + 0] = run; run += c0;
        soff[base + 1] = run; run += c1;
        if (tid == TPB - 1) soff[NB] = run;   // == NN
    }
    __syncthreads();

    // ---- P3: select this block's 8 buckets from x (few smem atomics) ----
    const int b0 = blk * 8;
    #pragma unroll 16
    for (int t = 0; t < NN / TPB; ++t) {
        float v = x[t * TPB + tid];
        unsigned lb = (unsigned)(bucket_of(v) - b0);
        if (lb < 8u) {
            int p = atomicAdd(&cur[lb], 1);
            if (p < BCAP) sbuck[lb][p] = v;
        }
    }
    __syncthreads();

    // ---- P4: rank-sort bucket w (warps 0-7; canonical -> deterministic) ----
    if (w < 8) {
        int b  = b0 + w;
        int lo = soff[b];
        int cnt = soff[b + 1] - lo;
        if (cnt > BCAP) cnt = BCAP;
        for (int t = lane; t < cnt; t += 32) {
            float val = sbuck[w][t];
            int rank = 0;
            for (int u = 0; u < cnt; ++u) {
                float o = sbuck[w][u];
                rank += (o < val) || (o == val && u < t);
            }
            g_sv[lo + rank] = val;
        }
    }

    gbar();  // B2: g_sv published; all g_hist reads done

    // reset histogram for the next graph replay (race-free after B2)
    if (tid < 8) g_hist[b0 + tid] = 0;

    // ---- P5: windowed KDE. 256 chunks of 32 sorted elems; block handles
    // chunks blk and blk+128; 8 warps per chunk take contiguous eighth-windows,
    // each staged into a per-warp smem buffer (coalesced LDG, then LDS.128).
    {
        const int slot  = w >> 3;            // 0/1 -> chunk A/B
        const int e8    = w & 7;             // eighth
        const int chunk = blk + GRID * slot; // 0..255
        const int i     = chunk * 32 + lane;

        float xi  = g_sv[i];
        float x0  = __shfl_sync(FULL, xi, 0);
        float x31 = __shfl_sync(FULL, xi, 31);
        int jlo = soff[max(bucket_of(x0)  - RWIN,     0)];
        int jhi = soff[min(bucket_of(x31) + RWIN + 1, NB)];
        int len   = jhi - jlo;
        int elen  = (len + 7) >> 3;          // eighth length
        int qs = jlo + e8 * elen;
        int qe = min(qs + elen, jhi);

        float a0 = 0.f, a1 = 0.f, a2 = 0.f, a3 = 0.f;
        float* wbp = wb[w];

        for (int base = qs; base < qe; base += WBUF) {
            int cnt = min(WBUF, qe - base);
            int pad = (cnt + 3) & ~3;
            // coalesced stage; pad with 1e30f -> d*d=inf -> EX2(-inf)=0.0f exactly
            for (int t = lane; t < pad; t += 32)
                wbp[t] = (t < cnt) ? g_sv[base + t] : 1e30f;
            __syncwarp();
            for (int k = 0; k < pad; k += 4) {
                float4 qv = *(const float4*)&wbp[k];
                float d0 = xi - qv.x, d1 = xi - qv.y, d2 = xi - qv.z, d3 = xi - qv.w;
                a0 += __expf(CEXP * d0 * d0);
                a1 += __expf(CEXP * d1 * d1);
                a2 += __expf(CEXP * d2 * d2);
                a3 += __expf(CEXP * d3 * d3);
            }
            __syncwarp();
        }
        kq[slot][e8][lane] = (a0 + a1) + (a2 + a3);
    }
    __syncthreads();

    // eighth combine + mixture + per-chunk warp reduction (warps 0 and 8)
    if ((w & 7) == 0) {
        const int slot  = w >> 3;
        const int chunk = blk + GRID * slot;
        const int i     = chunk * 32 + lane;
        float xi = g_sv[i];

        float kde = ((kq[slot][0][lane] + kq[slot][1][lane])
                   + (kq[slot][2][lane] + kq[slot][3][lane]))
                  + ((kq[slot][4][lane] + kq[slot][5][lane])
                   + (kq[slot][6][lane] + kq[slot][7][lane]));
        const float invZ = (float)(1.0 / (0.0078125 * 2.5066282746310002 * 8192.0));
        float data_pdf = kde * invZ;

        float mix = 0.0f;
        #pragma unroll 8
        for (int k = 0; k < KK; ++k) {
            float d = xi - smu[k];
            mix += sa[k] * __expf(sc[k] * d * d);
        }
        float diff = mix - data_pdf;
        float dd = diff * diff;
        #pragma unroll
        for (int o = 16; o > 0; o >>= 1) dd += __shfl_xor_sync(FULL, dd, o);
        if (lane == 0) rpair[slot] = dd;
    }
    __syncthreads();

    // ---- P6: publish partial; last block does fixed-order final sum ----
    if (tid == 0) {
        g_part[blk] = rpair[0] + rpair[1];
        __threadfence();
        int old = atomicAdd(&g_cnt, 1);
        slast = (((old + 1) & (GRID - 1)) == 0);
    }
    __syncthreads();

    if (slast) {
        if (tid < GRID) {
            volatile float* vp = g_part;    // bypass L1 (written by other SMs)
            fred[tid] = vp[tid];
        }
        __syncthreads();
        if (tid < GRID) {
            #pragma unroll
            for (int off = GRID / 2; off > 0; off >>= 1) {
                if (tid < off) fred[tid] += fred[tid + off];
                __syncthreads();
            }
        }
        if (tid == 0) out[0] = fred[0];
    }
}

// ---------------------------------------------------------------------------
extern "C" void kernel_launch(void* const* d_in, const int* in_sizes, int n_in,
                              void* d_out, int out_size)
{
    const float* x             = (const float*)d_in[0];
    const float* weight_logits = (const float*)d_in[1];
    const float* means         = (const float*)d_in[2];
    const float* log_vars      = (const float*)d_in[3];
    float* out = (float*)d_out;

    gmm_fused<<<GRID, TPB>>>(x, weight_logits, means, log_vars, out);
}

// round 11
// speedup vs baseline: 2.5744x; 1.0035x over previous
#include <cuda_runtime.h>
#include <cuda_bf16.h>
#include <math.h>

// Problem constants
#define NN 8192
#define KK 64
#define NB 1024
#define XLO (-6.0f)
#define BW_INVF (1024.0f / 12.0f)   // 1/bucket_width
#define RWIN 10                     // excluded pairs: |d| > 10*w = 0.1172 -> __expf == 0.0f exactly
#define CEXP (-8192.0f)             // -0.5/bw^2
#define GRID 128
#define TPB 512
#define NGRP 8                      // own buckets per block (stride 128 in bucket space)
#define NBIN (NGRP * 21)            // 168 local bins (own bucket +/- 10 per group)
#define SCAP 4096                   // staged capacity (typ ~1400)

// Persistent global state (monotonic counter survives graph replays)
__device__ int   g_cnt;
__device__ float g_part[GRID];

__device__ __forceinline__ int bucket_of(float v) {
    int b = (int)floorf((v - XLO) * BW_INVF);
    return min(max(b, 0), NB - 1);
}

__global__ void __launch_bounds__(TPB, 1)
gmm_fused(const float* __restrict__ x,
          const float* __restrict__ weight_logits,
          const float* __restrict__ means,
          const float* __restrict__ log_vars,
          float* __restrict__ out)
{
    __shared__ float raw[SCAP];                 // staged (atomic order)
    __shared__ float srt[SCAP];                 // staged (bin-major, value-sorted)
    __shared__ unsigned short bid[SCAP];        // bin id per staged slot
    __shared__ int   bcnt[NBIN];
    __shared__ int   boff[NBIN + 1];
    __shared__ int   bcur[NBIN];
    __shared__ int   ownoff[NGRP + 1];
    __shared__ float sa[KK], sc[KK], smu[KK];
    __shared__ float red[TPB / 32];
    __shared__ float fred[GRID];
    __shared__ int   slast;

    const int tid  = threadIdx.x;
    const int blk  = blockIdx.x;
    const int lane = tid & 31;
    const int w    = tid >> 5;
    const unsigned FULL = 0xffffffffu;

    // ---- GMM constants: every block computes redundantly (warp 0) ----
    if (w == 0) {
        const float TWO_PI = 6.283185307179586f;
        float l0 = weight_logits[lane], l1 = weight_logits[lane + 32];
        float m = fmaxf(l0, l1);
        #pragma unroll
        for (int o = 16; o > 0; o >>= 1) m = fmaxf(m, __shfl_xor_sync(FULL, m, o));
        float e0 = expf(l0 - m), e1 = expf(l1 - m);
        float s = e0 + e1;
        #pragma unroll
        for (int o = 16; o > 0; o >>= 1) s += __shfl_xor_sync(FULL, s, o);
        float invs = 1.0f / s;

        float var0 = expf(log_vars[lane]);
        sa[lane]  = e0 * invs * rsqrtf(TWO_PI * var0);
        sc[lane]  = -0.5f / var0;
        smu[lane] = means[lane];
        float var1 = expf(log_vars[lane + 32]);
        sa[lane + 32]  = e1 * invs * rsqrtf(TWO_PI * var1);
        sc[lane + 32]  = -0.5f / var1;
        smu[lane + 32] = means[lane + 32];
    }

    if (tid < NBIN) bcnt[tid] = 0;
    __syncthreads();

    // ---- P1: scan x, classify into local bins, count -------------------
    // Own buckets: {k*128 + blk, k=0..7}. Bin for bucket b: q = b+10-blk;
    // g = q>>7, r = q&127; keep iff q>=0 && r<=20 && g<8. bin = g*21+r.
    float vv[NN / TPB];
    int   vbin[NN / TPB];
    #pragma unroll
    for (int t = 0; t < NN / TPB; ++t) {
        float v = x[t * TPB + tid];
        int b = bucket_of(v);
        int q = b + RWIN - blk;
        int bin = -1;
        if (q >= 0) {
            int g = q >> 7, r = q & 127;
            if (r <= 2 * RWIN && g < NGRP) bin = g * 21 + r;
        }
        vv[t] = v; vbin[t] = bin;
        if (bin >= 0) atomicAdd(&bcnt[bin], 1);
    }
    __syncthreads();

    // ---- P2: prefix over 168 bins (warp 0) + own-bin prefix (warp 1) ----
    if (w == 0) {
        int base = lane * 6;
        int c[6]; int tot = 0;
        #pragma unroll
        for (int i = 0; i < 6; ++i) {
            int idx = base + i;
            c[i] = (idx < NBIN) ? bcnt[idx] : 0;
            tot += c[i];
        }
        int incl = tot;
        #pragma unroll
        for (int o = 1; o < 32; o <<= 1) {
            int n = __shfl_up_sync(FULL, incl, o);
            if (lane >= o) incl += n;
        }
        int run = incl - tot;
        #pragma unroll
        for (int i = 0; i < 6; ++i) {
            int idx = base + i;
            if (idx < NBIN) boff[idx] = run;
            run += c[i];
        }
        if (lane == 31) boff[NBIN] = incl;   // total staged S
    }
    if (w == 1 && lane < NGRP) {
        int oc = bcnt[lane * 21 + RWIN];     // own bucket bin (r=10)
        int incl = oc;
        #pragma unroll
        for (int o = 1; o < NGRP; o <<= 1) {
            int n = __shfl_up_sync(0xffu, incl, o, NGRP);
            if (lane >= o) incl += n;
        }
        ownoff[lane] = incl - oc;
        if (lane == NGRP - 1) ownoff[NGRP] = incl;
    }
    __syncthreads();
    if (tid < NBIN) bcur[tid] = boff[tid];
    __syncthreads();

    // ---- P3: place into raw[] (atomic order; canonicalized next) -------
    #pragma unroll
    for (int t = 0; t < NN / TPB; ++t) {
        int bin = vbin[t];
        if (bin >= 0) {
            int p = atomicAdd(&bcur[bin], 1);
            if (p < SCAP) { raw[p] = vv[t]; bid[p] = (unsigned short)bin; }
        }
    }
    __syncthreads();

    // ---- P4: element-parallel rank sort within bins (deterministic) ----
    const int S = boff[NBIN];
    for (int s = tid; s < S; s += TPB) {
        int bin = bid[s];
        int lo = boff[bin], hi = boff[bin + 1];
        float val = raw[s];
        int rank = 0;
        for (int u = lo; u < hi; ++u) {
            float o = raw[u];
            rank += (o < val) || (o == val && u < s);
        }
        srt[lo + rank] = val;
    }
    __syncthreads();

    // ---- P5: KDE + mixture. 8 threads per own element ------------------
    const float invZ = (float)(1.0 / (0.0078125 * 2.5066282746310002 * 8192.0));
    const int M   = ownoff[NGRP];
    const int Mup = (M + 63) & ~63;
    const int e0  = tid >> 3;
    const int p   = tid & 7;

    float acc = 0.0f;
    for (int e = e0; e < Mup; e += TPB / 8) {
        bool active = (e < M);
        int g = 0;
        #pragma unroll
        for (int q = 1; q < NGRP; ++q) if (active && e >= ownoff[q]) g = q;

        float xi = 0.0f;
        int wlo = 0, whi = 0;
        if (active) {
            int pos = e - ownoff[g];
            xi  = srt[boff[g * 21 + RWIN] + pos];
            wlo = boff[g * 21];
            whi = boff[g * 21 + 21];
        }

        // this part's strided share of the group window
        float s0 = 0.f, s1 = 0.f;
        int t = wlo + p;
        for (; t + 8 < whi; t += 16) {
            float d0 = xi - srt[t];
            float d1 = xi - srt[t + 8];
            s0 += __expf(CEXP * d0 * d0);
            s1 += __expf(CEXP * d1 * d1);
        }
        for (; t < whi; t += 8) {
            float d = xi - srt[t];
            s0 += __expf(CEXP * d * d);
        }
        float kde = s0 + s1;

        // this part's 8 mixture components
        float m = 0.0f;
        #pragma unroll
        for (int k = p * 8; k < p * 8 + 8; ++k) {
            float d = xi - smu[k];
            m += sa[k] * __expf(sc[k] * d * d);
        }

        float part = active ? (m - invZ * kde) : 0.0f;
        // combine the 8 parts (fixed order; width-8 butterfly)
        part += __shfl_xor_sync(FULL, part, 4, 8);
        part += __shfl_xor_sync(FULL, part, 2, 8);
        part += __shfl_xor_sync(FULL, part, 1, 8);
        if (p == 0 && active) acc += part * part;
    }

    // ---- block reduction (fixed order) ---------------------------------
    #pragma unroll
    for (int o = 16; o > 0; o >>= 1) acc += __shfl_xor_sync(FULL, acc, o);
    if (lane == 0) red[w] = acc;
    __syncthreads();
    if (w == 0) {
        float bsum = (lane < TPB / 32) ? red[lane] : 0.0f;
        #pragma unroll
        for (int o = 16; o > 0; o >>= 1) bsum += __shfl_xor_sync(FULL, bsum, o);
        if (lane == 0) {
            g_part[blk] = bsum;
            __threadfence();
            int old = atomicAdd(&g_cnt, 1);
            slast = (((old + 1) & (GRID - 1)) == 0);
        }
    }
    __syncthreads();

    // ---- last block: fixed-order final sum ------------------------------
    if (slast) {
        if (tid < GRID) {
            volatile float* vp = g_part;
            fred[tid] = vp[tid];
        }
        __syncthreads();
        #pragma unroll
        for (int off = GRID / 2; off > 0; off >>= 1) {
            if (tid < off) fred[tid] += fred[tid + off];
            __syncthreads();
        }
        if (tid == 0) out[0] = fred[0];
    }
}

// ---------------------------------------------------------------------------
extern "C" void kernel_launch(void* const* d_in, const int* in_sizes, int n_in,
                              void* d_out, int out_size)
{
    const float* x             = (const float*)d_in[0];
    const float* weight_logits = (const float*)d_in[1];
    const float* means         = (const float*)d_in[2];
    const float* log_vars      = (const float*)d_in[3];
    float* out = (float*)d_out;

    gmm_fused<<<GRID, TPB>>>(x, weight_logits, means, log_vars, out);
}